// round 8
// baseline (speedup 1.0000x reference)
#include <cuda_runtime.h>
#include <math.h>

#define EPSF 1e-8f
#define BIGF 1e10f
#define MAXB 8
#define MAXF 4096

#define TILE_W 8
#define TILE_H 8
#define NT_R   32          // raster threads: 4 col-threads*2px x 8 rows
#define NT     128

#define MAXBL    4         // batches supported by the bin lists
#define MAXTILES 1024      // 32x32 tiles for 256x256 at 8x8
#define CAP      2048      // per-tile list capacity (>= F always)
#define CH       64        // chunk size (entries per staged inner loop)

// Scratch (device globals; no dynamic allocation allowed)
__device__ float4 g_tri[MAXB * MAXF * 4];     // d0,d1,d2,d3 per triangle
__device__ float4 g_bbox[MAXB * MAXF];        // xmin,xmax,ymin,ymax
__device__ int    g_cnt[MAXB];
__device__ int    g_tilecnt[MAXBL * MAXTILES];
__device__ int    g_tilelist[MAXBL * MAXTILES * CAP];

__global__ void dr_init_kernel(int ntile_tot) {
    int i = blockIdx.x * blockDim.x + threadIdx.x;
    if (i < MAXB) g_cnt[i] = 0;
    for (int j = i; j < ntile_tot; j += gridDim.x * blockDim.x) g_tilecnt[j] = 0;
}

// One thread per (batch, face): project 3 vertices, build edge-function setup,
// cull invalid triangles, append to compacted list.
__global__ void dr_setup_kernel(const float* __restrict__ mesh,
                                const float* __restrict__ Rm,
                                const float* __restrict__ tv,
                                const float* __restrict__ focal,
                                const float* __restrict__ princpt,
                                const int*   __restrict__ face,
                                int B, int V, int F) {
    int idx = blockIdx.x * blockDim.x + threadIdx.x;
    if (idx >= B * F) return;
    int b = idx / F;
    int f = idx - b * F;

    const float* Rb = Rm + b * 9;
    float t0 = tv[b * 3 + 0], t1 = tv[b * 3 + 1], t2 = tv[b * 3 + 2];
    float fx = focal[b * 2 + 0], fy = focal[b * 2 + 1];
    float cx = princpt[b * 2 + 0], cy = princpt[b * 2 + 1];

    float X[3], Y[3], Z[3];
#pragma unroll
    for (int k = 0; k < 3; k++) {
        int v = face[f * 3 + k];
        const float* m = mesh + ((long)b * V + v) * 3;
        float m0 = m[0], m1 = m[1], m2 = m[2];
        // einsum sum order j=0..2, then + t  (exact rn ops, no contraction)
        float c0 = __fadd_rn(__fadd_rn(__fmul_rn(Rb[0], m0), __fmul_rn(Rb[1], m1)), __fmul_rn(Rb[2], m2));
        float c1 = __fadd_rn(__fadd_rn(__fmul_rn(Rb[3], m0), __fmul_rn(Rb[4], m1)), __fmul_rn(Rb[5], m2));
        float c2 = __fadd_rn(__fadd_rn(__fmul_rn(Rb[6], m0), __fmul_rn(Rb[7], m1)), __fmul_rn(Rb[8], m2));
        c0 = __fadd_rn(c0, t0);
        c1 = __fadd_rn(c1, t1);
        c2 = __fadd_rn(c2, t2);
        float zs = (fabsf(c2) > EPSF) ? c2 : EPSF;
        X[k] = __fadd_rn(__fdiv_rn(__fmul_rn(fx, c0), zs), cx);
        Y[k] = __fadd_rn(__fdiv_rn(__fmul_rn(fy, c1), zs), cy);
        Z[k] = c2;
    }

    // area = (x1-x0)*(y2-y0) - (y1-y0)*(x2-x0)   (reference rounding)
    float area = __fsub_rn(__fmul_rn(__fsub_rn(X[1], X[0]), __fsub_rn(Y[2], Y[0])),
                           __fmul_rn(__fsub_rn(Y[1], Y[0]), __fsub_rn(X[2], X[0])));
    if (!(fabsf(area) > EPSF)) return;                       // invalid area -> never contributes
    if (!(fminf(Z[0], fminf(Z[1], Z[2])) > EPSF)) return;    // not front -> never contributes

    float iz0 = __fdiv_rn(Z[0], area);
    float iz1 = __fdiv_rn(Z[1], area);
    float iz2 = __fdiv_rn(Z[2], area);

    int p = atomicAdd(&g_cnt[b], 1);
    float4* o = &g_tri[((long)b * MAXF + p) * 4];
    // w0 = (x2-x1)*(py-y1) - (y2-y1)*(px-x1)  -> (e0x, e0y, x1, y1)
    o[0] = make_float4(__fsub_rn(X[2], X[1]), __fsub_rn(Y[2], Y[1]), X[1], Y[1]);
    // w1 = (x0-x2)*(py-y2) - (y0-y2)*(px-x2)  -> (e1x, e1y, x2, y2)
    o[1] = make_float4(__fsub_rn(X[0], X[2]), __fsub_rn(Y[0], Y[2]), X[2], Y[2]);
    // w2 = (x1-x0)*(py-y0) - (y1-y0)*(px-x0)  -> (e2x, e2y, x0, y0)
    o[2] = make_float4(__fsub_rn(X[1], X[0]), __fsub_rn(Y[1], Y[0]), X[0], Y[0]);
    o[3] = make_float4(iz0, iz1, iz2, 0.f);

    float xmin = fminf(X[0], fminf(X[1], X[2]));
    float xmax = fmaxf(X[0], fmaxf(X[1], X[2]));
    float ymin = fminf(Y[0], fminf(Y[1], Y[2]));
    float ymax = fmaxf(Y[0], fmaxf(Y[1], Y[2]));
    g_bbox[(long)b * MAXF + p] = make_float4(xmin, xmax, ymin, ymax);
}

// Conservative interval of affine w over a pixel-center rectangle:
// wc at rect center, radius = |ex|*hy + |ey|*hx, padded for fp slop.
__device__ __forceinline__ void edge_range(float ex, float ey, float ax, float ay,
                                           float cx, float cy, float hx, float hy,
                                           float& wmin, float& wmax) {
    float wc = ex * (cy - ay) - ey * (cx - ax);
    float r  = fabsf(ex) * hy + fabsf(ey) * hx;
    float pad = 1e-5f * (fabsf(wc) + r) + 1e-5f;
    wmin = wc - r - pad;
    wmax = wc + r + pad;
}

__device__ __forceinline__ bool rect_may_hit(float4 e0, float4 e1, float4 e2,
                                             float cx, float cy, float hx, float hy) {
    float mn0, mx0, mn1, mx1, mn2, mx2;
    edge_range(e0.x, e0.y, e0.z, e0.w, cx, cy, hx, hy, mn0, mx0);
    edge_range(e1.x, e1.y, e1.z, e1.w, cx, cy, hx, hy, mn1, mx1);
    edge_range(e2.x, e2.y, e2.z, e2.w, cx, cy, hx, hy, mn2, mx2);
    bool pos_ok = (mx0 >= 0.f) && (mx1 >= 0.f) && (mx2 >= 0.f);
    bool neg_ok = (mn0 <= 0.f) && (mn1 <= 0.f) && (mn2 <= 0.f);
    return pos_ok || neg_ok;
}

// One warp per compacted triangle: lanes walk candidate tiles from the bbox
// range, apply bbox + edge-interval test, push index into per-tile list.
__global__ __launch_bounds__(NT)
void dr_bin_kernel(int ntx, int nty) {
    int warp = threadIdx.x >> 5;
    int lane = threadIdx.x & 31;
    int b = blockIdx.y;
    int t = blockIdx.x * (NT / 32) + warp;
    if (t >= g_cnt[b]) return;

    float4 bb = g_bbox[(long)b * MAXF + t];
    const float4* s = &g_tri[((long)b * MAXF + t) * 4];
    float4 e0 = s[0], e1 = s[1], e2 = s[2];

    // conservative candidate tile range (extra tiles rejected by tests below)
    int tx0 = max(0, (int)floorf((bb.x - ((float)TILE_W - 0.5f)) * (1.f / TILE_W)));
    int tx1 = min(ntx - 1, (int)floorf((bb.y - 0.5f) * (1.f / TILE_W)) + 1);
    int ty0 = max(0, (int)floorf((bb.z - ((float)TILE_H - 0.5f)) * (1.f / TILE_H)));
    int ty1 = min(nty - 1, (int)floorf((bb.w - 0.5f) * (1.f / TILE_H)) + 1);
    if (tx1 < tx0 || ty1 < ty0) return;
    int nx = tx1 - tx0 + 1;
    int ntiles = nx * (ty1 - ty0 + 1);

    for (int i = lane; i < ntiles; i += 32) {
        int tilex = tx0 + (i % nx);
        int tiley = ty0 + (i / nx);
        float tminx = (float)(tilex * TILE_W) + 0.5f;
        float tmaxx = (float)(tilex * TILE_W + TILE_W - 1) + 0.5f;
        float tminy = (float)(tiley * TILE_H) + 0.5f;
        float tmaxy = (float)(tiley * TILE_H + TILE_H - 1) + 0.5f;
        // bbox pre-filter (same as before)
        if (bb.y >= tminx && bb.x <= tmaxx && bb.w >= tminy && bb.z <= tmaxy) {
            float tcx = 0.5f * (tminx + tmaxx);
            float tcy = 0.5f * (tminy + tmaxy);
            float thx = 0.5f * (tmaxx - tminx);
            float thy = 0.5f * (tmaxy - tminy);
            if (rect_may_hit(e0, e1, e2, tcx, tcy, thx, thy)) {
                int tile = tiley * ntx + tilex;
                int slot = b * MAXTILES + tile;
                int p = atomicAdd(&g_tilecnt[slot], 1);   // p < cnt <= CAP always
                g_tilelist[(long)slot * CAP + p] = t;
            }
        }
    }
}

// 8x8 pixel tile, 32 threads, 2 adjacent px/thread. One block per (batch,tile);
// block owns its pixels exclusively -> direct write to out, no z-buffer merge.
__global__ __launch_bounds__(NT_R)
void dr_raster_kernel(float* __restrict__ out, int W, int H, int ntx) {
    __shared__ float4 sdata[CH * 4];
    __shared__ int    sidx[CH];

    int b = blockIdx.z;
    int tile = blockIdx.y * ntx + blockIdx.x;
    int count = g_tilecnt[b * MAXTILES + tile];

    int tid = threadIdx.x;
    int tx = tid & 3;        // 4 column-threads * 2 px = 8 cols
    int ty = tid >> 2;       // 8 rows

    int row  = blockIdx.y * TILE_H + ty;
    int col0 = blockIdx.x * TILE_W + tx * 2;
    float py  = (float)row + 0.5f;
    float px0 = (float)col0 + 0.5f;
    float px1 = px0 + 1.0f;

    float zmin0 = BIGF, zmin1 = BIGF;

    const int*    list = &g_tilelist[((long)b * MAXTILES + tile) * CAP];
    const float4* tri  = &g_tri[(long)b * MAXF * 4];

    for (int base = 0; base < count; base += CH) {
        int n = min(CH, count - base);
        // stage indices
        for (int i = tid; i < n; i += NT_R) sidx[i] = list[base + i];
        __syncthreads();
        // stage triangle data (4 float4 per entry)
        for (int i = tid; i < n * 4; i += NT_R)
            sdata[i] = tri[(long)sidx[i >> 2] * 4 + (i & 3)];
        __syncthreads();

        for (int j = 0; j < n; j++) {
            float4 d0 = sdata[j * 4 + 0];
            float4 d1 = sdata[j * 4 + 1];
            float4 d2 = sdata[j * 4 + 2];
            float4 d3 = sdata[j * 4 + 3];
            // row-shared terms (reference rounding preserved)
            float a0 = __fmul_rn(d0.x, __fsub_rn(py, d0.w));
            float a1 = __fmul_rn(d1.x, __fsub_rn(py, d1.w));
            float a2 = __fmul_rn(d2.x, __fsub_rn(py, d2.w));
            // pixel 0
            {
                float w0 = __fsub_rn(a0, __fmul_rn(d0.y, __fsub_rn(px0, d0.z)));
                float w1 = __fsub_rn(a1, __fmul_rn(d1.y, __fsub_rn(px0, d1.z)));
                float w2 = __fsub_rn(a2, __fmul_rn(d2.y, __fsub_rn(px0, d2.z)));
                float wmn = fminf(fminf(w0, w1), w2);
                float wmx = fmaxf(fmaxf(w0, w1), w2);
                bool inside = (wmn >= 0.f) || (wmx <= 0.f);
                float zi = __fmaf_rn(w0, d3.x, __fmaf_rn(w1, d3.y, __fmul_rn(w2, d3.z)));
                if (inside && zi > EPSF) zmin0 = fminf(zmin0, zi);
            }
            // pixel 1
            {
                float w0 = __fsub_rn(a0, __fmul_rn(d0.y, __fsub_rn(px1, d0.z)));
                float w1 = __fsub_rn(a1, __fmul_rn(d1.y, __fsub_rn(px1, d1.z)));
                float w2 = __fsub_rn(a2, __fmul_rn(d2.y, __fsub_rn(px1, d2.z)));
                float wmn = fminf(fminf(w0, w1), w2);
                float wmx = fmaxf(fmaxf(w0, w1), w2);
                bool inside = (wmn >= 0.f) || (wmx <= 0.f);
                float zi = __fmaf_rn(w0, d3.x, __fmaf_rn(w1, d3.y, __fmul_rn(w2, d3.z)));
                if (inside && zi > EPSF) zmin1 = fminf(zmin1, zi);
            }
        }
        __syncthreads();
    }

    if (row < H) {
        float2 r;
        r.x = (zmin0 < 0.5f * BIGF) ? zmin0 : -1.f;
        r.y = (zmin1 < 0.5f * BIGF) ? zmin1 : -1.f;
        long off = ((long)b * H + row) * W + col0;
        if (col0 + 1 < W) {
            *(float2*)&out[off] = r;
        } else if (col0 < W) {
            out[off] = r.x;
        }
    }
}

extern "C" void kernel_launch(void* const* d_in, const int* in_sizes, int n_in,
                              void* d_out, int out_size) {
    const float* mesh    = (const float*)d_in[0];
    const float* Rm      = (const float*)d_in[1];
    const float* tv      = (const float*)d_in[2];
    const float* focal   = (const float*)d_in[3];
    const float* princpt = (const float*)d_in[4];
    const int*   face    = (const int*)  d_in[5];
    float* out = (float*)d_out;

    int B = in_sizes[1] / 9;            // R is (B,3,3)
    int V = in_sizes[0] / (3 * B);      // mesh is (B,V,3)
    int F = in_sizes[5] / 3;            // face is (F,3)
    int HW = out_size / B;              // out is (B,1,H,W)
    int W = (int)(sqrt((double)HW) + 0.5);
    int H = HW / W;
    int ntx = (W + TILE_W - 1) / TILE_W;
    int nty = (H + TILE_H - 1) / TILE_H;

    dr_init_kernel<<<16, 256>>>(B * MAXTILES);
    int nset = B * F;
    dr_setup_kernel<<<(nset + 255) / 256, 256>>>(mesh, Rm, tv, focal, princpt, face, B, V, F);
    dim3 bgrid((F + (NT / 32) - 1) / (NT / 32), B);
    dr_bin_kernel<<<bgrid, NT>>>(ntx, nty);
    dim3 grid(ntx, nty, B);
    dr_raster_kernel<<<grid, NT_R>>>(out, W, H, ntx);
}

// round 9
// speedup vs baseline: 1.1971x; 1.1971x over previous
#include <cuda_runtime.h>
#include <math.h>

#define EPSF 1e-8f
#define BIGF 1e10f
#define MAXB 8
#define MAXF 4096

#define TILE_W 8
#define TILE_H 8
#define NT_R   128         // 4 warps; each warp covers all 64 px, 1/4 of list
#define NWARPS 4
#define NT     128

#define MAXBL    4         // batches supported by the bin lists
#define MAXTILES 1024      // 32x32 tiles for 256x256 at 8x8
#define CAP      2048      // per-tile list capacity (>= F always)
#define CH       32        // per-warp chunk size

// Scratch (device globals; no dynamic allocation allowed)
__device__ float4 g_tri[MAXB * MAXF * 4];     // d0,d1,d2,d3 per triangle
__device__ float4 g_bbox[MAXB * MAXF];        // xmin,xmax,ymin,ymax
__device__ int    g_cnt[MAXB];
__device__ int    g_tilecnt[MAXBL * MAXTILES];
__device__ int    g_tilelist[MAXBL * MAXTILES * CAP];

__global__ void dr_init_kernel(int ntile_tot) {
    int i = blockIdx.x * blockDim.x + threadIdx.x;
    if (i < MAXB) g_cnt[i] = 0;
    for (int j = i; j < ntile_tot; j += gridDim.x * blockDim.x) g_tilecnt[j] = 0;
}

// One thread per (batch, face): project 3 vertices, build edge-function setup,
// cull invalid triangles, append to compacted list.
__global__ void dr_setup_kernel(const float* __restrict__ mesh,
                                const float* __restrict__ Rm,
                                const float* __restrict__ tv,
                                const float* __restrict__ focal,
                                const float* __restrict__ princpt,
                                const int*   __restrict__ face,
                                int B, int V, int F) {
    int idx = blockIdx.x * blockDim.x + threadIdx.x;
    if (idx >= B * F) return;
    int b = idx / F;
    int f = idx - b * F;

    const float* Rb = Rm + b * 9;
    float t0 = tv[b * 3 + 0], t1 = tv[b * 3 + 1], t2 = tv[b * 3 + 2];
    float fx = focal[b * 2 + 0], fy = focal[b * 2 + 1];
    float cx = princpt[b * 2 + 0], cy = princpt[b * 2 + 1];

    float X[3], Y[3], Z[3];
#pragma unroll
    for (int k = 0; k < 3; k++) {
        int v = face[f * 3 + k];
        const float* m = mesh + ((long)b * V + v) * 3;
        float m0 = m[0], m1 = m[1], m2 = m[2];
        // einsum sum order j=0..2, then + t  (exact rn ops, no contraction)
        float c0 = __fadd_rn(__fadd_rn(__fmul_rn(Rb[0], m0), __fmul_rn(Rb[1], m1)), __fmul_rn(Rb[2], m2));
        float c1 = __fadd_rn(__fadd_rn(__fmul_rn(Rb[3], m0), __fmul_rn(Rb[4], m1)), __fmul_rn(Rb[5], m2));
        float c2 = __fadd_rn(__fadd_rn(__fmul_rn(Rb[6], m0), __fmul_rn(Rb[7], m1)), __fmul_rn(Rb[8], m2));
        c0 = __fadd_rn(c0, t0);
        c1 = __fadd_rn(c1, t1);
        c2 = __fadd_rn(c2, t2);
        float zs = (fabsf(c2) > EPSF) ? c2 : EPSF;
        X[k] = __fadd_rn(__fdiv_rn(__fmul_rn(fx, c0), zs), cx);
        Y[k] = __fadd_rn(__fdiv_rn(__fmul_rn(fy, c1), zs), cy);
        Z[k] = c2;
    }

    // area = (x1-x0)*(y2-y0) - (y1-y0)*(x2-x0)   (reference rounding)
    float area = __fsub_rn(__fmul_rn(__fsub_rn(X[1], X[0]), __fsub_rn(Y[2], Y[0])),
                           __fmul_rn(__fsub_rn(Y[1], Y[0]), __fsub_rn(X[2], X[0])));
    if (!(fabsf(area) > EPSF)) return;                       // invalid area -> never contributes
    if (!(fminf(Z[0], fminf(Z[1], Z[2])) > EPSF)) return;    // not front -> never contributes

    float iz0 = __fdiv_rn(Z[0], area);
    float iz1 = __fdiv_rn(Z[1], area);
    float iz2 = __fdiv_rn(Z[2], area);

    int p = atomicAdd(&g_cnt[b], 1);
    float4* o = &g_tri[((long)b * MAXF + p) * 4];
    // w0 = (x2-x1)*(py-y1) - (y2-y1)*(px-x1)  -> (e0x, e0y, x1, y1)
    o[0] = make_float4(__fsub_rn(X[2], X[1]), __fsub_rn(Y[2], Y[1]), X[1], Y[1]);
    // w1 = (x0-x2)*(py-y2) - (y0-y2)*(px-x2)  -> (e1x, e1y, x2, y2)
    o[1] = make_float4(__fsub_rn(X[0], X[2]), __fsub_rn(Y[0], Y[2]), X[2], Y[2]);
    // w2 = (x1-x0)*(py-y0) - (y1-y0)*(px-x0)  -> (e2x, e2y, x0, y0)
    o[2] = make_float4(__fsub_rn(X[1], X[0]), __fsub_rn(Y[1], Y[0]), X[0], Y[0]);
    o[3] = make_float4(iz0, iz1, iz2, 0.f);

    float xmin = fminf(X[0], fminf(X[1], X[2]));
    float xmax = fmaxf(X[0], fmaxf(X[1], X[2]));
    float ymin = fminf(Y[0], fminf(Y[1], Y[2]));
    float ymax = fmaxf(Y[0], fmaxf(Y[1], Y[2]));
    g_bbox[(long)b * MAXF + p] = make_float4(xmin, xmax, ymin, ymax);
}

// Conservative interval of affine w over a pixel-center rectangle:
// wc at rect center, radius = |ex|*hy + |ey|*hx, padded for fp slop.
__device__ __forceinline__ void edge_range(float ex, float ey, float ax, float ay,
                                           float cx, float cy, float hx, float hy,
                                           float& wmin, float& wmax) {
    float wc = ex * (cy - ay) - ey * (cx - ax);
    float r  = fabsf(ex) * hy + fabsf(ey) * hx;
    float pad = 1e-5f * (fabsf(wc) + r) + 1e-5f;
    wmin = wc - r - pad;
    wmax = wc + r + pad;
}

__device__ __forceinline__ bool rect_may_hit(float4 e0, float4 e1, float4 e2,
                                             float cx, float cy, float hx, float hy) {
    float mn0, mx0, mn1, mx1, mn2, mx2;
    edge_range(e0.x, e0.y, e0.z, e0.w, cx, cy, hx, hy, mn0, mx0);
    edge_range(e1.x, e1.y, e1.z, e1.w, cx, cy, hx, hy, mn1, mx1);
    edge_range(e2.x, e2.y, e2.z, e2.w, cx, cy, hx, hy, mn2, mx2);
    bool pos_ok = (mx0 >= 0.f) && (mx1 >= 0.f) && (mx2 >= 0.f);
    bool neg_ok = (mn0 <= 0.f) && (mn1 <= 0.f) && (mn2 <= 0.f);
    return pos_ok || neg_ok;
}

// One warp per compacted triangle: lanes walk candidate tiles from the bbox
// range, apply bbox + edge-interval test, push index into per-tile list.
__global__ __launch_bounds__(NT)
void dr_bin_kernel(int ntx, int nty) {
    int warp = threadIdx.x >> 5;
    int lane = threadIdx.x & 31;
    int b = blockIdx.y;
    int t = blockIdx.x * (NT / 32) + warp;
    if (t >= g_cnt[b]) return;

    float4 bb = g_bbox[(long)b * MAXF + t];
    const float4* s = &g_tri[((long)b * MAXF + t) * 4];
    float4 e0 = s[0], e1 = s[1], e2 = s[2];

    // conservative candidate tile range (extra tiles rejected by tests below)
    int tx0 = max(0, (int)floorf((bb.x - ((float)TILE_W - 0.5f)) * (1.f / TILE_W)));
    int tx1 = min(ntx - 1, (int)floorf((bb.y - 0.5f) * (1.f / TILE_W)) + 1);
    int ty0 = max(0, (int)floorf((bb.z - ((float)TILE_H - 0.5f)) * (1.f / TILE_H)));
    int ty1 = min(nty - 1, (int)floorf((bb.w - 0.5f) * (1.f / TILE_H)) + 1);
    if (tx1 < tx0 || ty1 < ty0) return;
    int nx = tx1 - tx0 + 1;
    int ntiles = nx * (ty1 - ty0 + 1);

    for (int i = lane; i < ntiles; i += 32) {
        int tilex = tx0 + (i % nx);
        int tiley = ty0 + (i / nx);
        float tminx = (float)(tilex * TILE_W) + 0.5f;
        float tmaxx = (float)(tilex * TILE_W + TILE_W - 1) + 0.5f;
        float tminy = (float)(tiley * TILE_H) + 0.5f;
        float tmaxy = (float)(tiley * TILE_H + TILE_H - 1) + 0.5f;
        // bbox pre-filter (same as before)
        if (bb.y >= tminx && bb.x <= tmaxx && bb.w >= tminy && bb.z <= tmaxy) {
            float tcx = 0.5f * (tminx + tmaxx);
            float tcy = 0.5f * (tminy + tmaxy);
            float thx = 0.5f * (tmaxx - tminx);
            float thy = 0.5f * (tmaxy - tminy);
            if (rect_may_hit(e0, e1, e2, tcx, tcy, thx, thy)) {
                int tile = tiley * ntx + tilex;
                int slot = b * MAXTILES + tile;
                int p = atomicAdd(&g_tilecnt[slot], 1);   // p < cnt <= CAP always
                g_tilelist[(long)slot * CAP + p] = t;
            }
        }
    }
}

// 8x8 pixel tile per block, 128 threads = 4 warps. Every warp covers all 64
// pixels (2 adjacent px/lane) but processes a disjoint quarter of the tile's
// triangle list (interleaved CH-chunks, per-warp SMEM staging). Partial z-mins
// merge in SMEM (fminf, order-independent) then write directly to out.
__global__ __launch_bounds__(NT_R)
void dr_raster_kernel(float* __restrict__ out, int W, int H, int ntx) {
    __shared__ float4 sdata[NWARPS][CH * 4];
    __shared__ int    sidx[NWARPS][CH];
    __shared__ float  szmin[NWARPS][65];   // [warp][pixel], padded

    int b = blockIdx.z;
    int tile = blockIdx.y * ntx + blockIdx.x;
    int count = g_tilecnt[b * MAXTILES + tile];

    int tid  = threadIdx.x;
    int warp = tid >> 5;
    int lane = tid & 31;
    // lane -> 2 adjacent pixels on one row: p0 = 2*lane, p1 = 2*lane+1
    int p0 = lane * 2;
    int prow = p0 >> 3;          // 0..7
    int pcol = p0 & 7;           // 0,2,4,6

    int row  = blockIdx.y * TILE_H + prow;
    int col0 = blockIdx.x * TILE_W + pcol;
    float py  = (float)row + 0.5f;
    float px0 = (float)col0 + 0.5f;
    float px1 = px0 + 1.0f;

    float zmin0 = BIGF, zmin1 = BIGF;

    const int*    list = &g_tilelist[((long)b * MAXTILES + tile) * CAP];
    const float4* tri  = &g_tri[(long)b * MAXF * 4];

    // warp w processes chunks w, w+4, w+8, ...
    for (int base = warp * CH; base < count; base += NWARPS * CH) {
        int n = min(CH, count - base);
        if (lane < n) sidx[warp][lane] = list[base + lane];
        __syncwarp();
        for (int i = lane; i < n * 4; i += 32)
            sdata[warp][i] = tri[(long)sidx[warp][i >> 2] * 4 + (i & 3)];
        __syncwarp();

        for (int j = 0; j < n; j++) {
            float4 d0 = sdata[warp][j * 4 + 0];
            float4 d1 = sdata[warp][j * 4 + 1];
            float4 d2 = sdata[warp][j * 4 + 2];
            float4 d3 = sdata[warp][j * 4 + 3];
            // row-shared terms (reference rounding preserved)
            float a0 = __fmul_rn(d0.x, __fsub_rn(py, d0.w));
            float a1 = __fmul_rn(d1.x, __fsub_rn(py, d1.w));
            float a2 = __fmul_rn(d2.x, __fsub_rn(py, d2.w));
            // pixel 0
            {
                float w0 = __fsub_rn(a0, __fmul_rn(d0.y, __fsub_rn(px0, d0.z)));
                float w1 = __fsub_rn(a1, __fmul_rn(d1.y, __fsub_rn(px0, d1.z)));
                float w2 = __fsub_rn(a2, __fmul_rn(d2.y, __fsub_rn(px0, d2.z)));
                float wmn = fminf(fminf(w0, w1), w2);
                float wmx = fmaxf(fmaxf(w0, w1), w2);
                bool inside = (wmn >= 0.f) || (wmx <= 0.f);
                float zi = __fmaf_rn(w0, d3.x, __fmaf_rn(w1, d3.y, __fmul_rn(w2, d3.z)));
                if (inside && zi > EPSF) zmin0 = fminf(zmin0, zi);
            }
            // pixel 1
            {
                float w0 = __fsub_rn(a0, __fmul_rn(d0.y, __fsub_rn(px1, d0.z)));
                float w1 = __fsub_rn(a1, __fmul_rn(d1.y, __fsub_rn(px1, d1.z)));
                float w2 = __fsub_rn(a2, __fmul_rn(d2.y, __fsub_rn(px1, d2.z)));
                float wmn = fminf(fminf(w0, w1), w2);
                float wmx = fmaxf(fmaxf(w0, w1), w2);
                bool inside = (wmn >= 0.f) || (wmx <= 0.f);
                float zi = __fmaf_rn(w0, d3.x, __fmaf_rn(w1, d3.y, __fmul_rn(w2, d3.z)));
                if (inside && zi > EPSF) zmin1 = fminf(zmin1, zi);
            }
        }
        __syncwarp();
    }

    // merge 4 warps' partial minima
    szmin[warp][p0]     = zmin0;
    szmin[warp][p0 + 1] = zmin1;
    __syncthreads();

    if (tid < 64) {
        int p = tid;
        float z = fminf(fminf(szmin[0][p], szmin[1][p]),
                        fminf(szmin[2][p], szmin[3][p]));
        int r = blockIdx.y * TILE_H + (p >> 3);
        int c = blockIdx.x * TILE_W + (p & 7);
        if (r < H && c < W) {
            long off = ((long)b * H + r) * W + c;
            out[off] = (z < 0.5f * BIGF) ? z : -1.f;
        }
    }
}

extern "C" void kernel_launch(void* const* d_in, const int* in_sizes, int n_in,
                              void* d_out, int out_size) {
    const float* mesh    = (const float*)d_in[0];
    const float* Rm      = (const float*)d_in[1];
    const float* tv      = (const float*)d_in[2];
    const float* focal   = (const float*)d_in[3];
    const float* princpt = (const float*)d_in[4];
    const int*   face    = (const int*)  d_in[5];
    float* out = (float*)d_out;

    int B = in_sizes[1] / 9;            // R is (B,3,3)
    int V = in_sizes[0] / (3 * B);      // mesh is (B,V,3)
    int F = in_sizes[5] / 3;            // face is (F,3)
    int HW = out_size / B;              // out is (B,1,H,W)
    int W = (int)(sqrt((double)HW) + 0.5);
    int H = HW / W;
    int ntx = (W + TILE_W - 1) / TILE_W;
    int nty = (H + TILE_H - 1) / TILE_H;

    dr_init_kernel<<<16, 256>>>(B * MAXTILES);
    int nset = B * F;
    dr_setup_kernel<<<(nset + 255) / 256, 256>>>(mesh, Rm, tv, focal, princpt, face, B, V, F);
    dim3 bgrid((F + (NT / 32) - 1) / (NT / 32), B);
    dr_bin_kernel<<<bgrid, NT>>>(ntx, nty);
    dim3 grid(ntx, nty, B);
    dr_raster_kernel<<<grid, NT_R>>>(out, W, H, ntx);
}